// round 2
// baseline (speedup 1.0000x reference)
#include <cuda_runtime.h>

#define S_LEN 4096
#define TWO_PI_F 6.28318530717958647692f

// Reciprocal-period tables, [i][j] layout (contiguous in j, matching weights)
__device__ float g_rpD[128 * 128];   // 1/(i*128+j+2)
__device__ float g_rpV[64 * 64];     // 1/(i*64+j+2)

__global__ void prep_kernel()
{
    int t = blockIdx.x * blockDim.x + threadIdx.x;
    if (t < 16384) { int i = t >> 7, j = t & 127; g_rpD[t] = 1.0f / (float)(i * 128 + j + 2); }
    if (t < 4096)  { int i = t >> 6, j = t & 63;  g_rpV[t] = 1.0f / (float)(i * 64 + j + 2); }
}

// cos(2*pi*s/p) via s*rp, exact-frac with fma, __cosf on [-pi,pi]
__device__ __forceinline__ float pcos(float sf, float rp)
{
    float f = sf * rp;
    float n = rintf(f);
    float r = fmaf(sf, rp, -n);
    return __cosf(TWO_PI_F * r);
}

__device__ __forceinline__ float warpsum(float v)
{
#pragma unroll
    for (int o = 16; o > 0; o >>= 1) v += __shfl_xor_sync(0xffffffffu, v, o);
    return v;
}

__global__ __launch_bounds__(512, 2)
void hier_kernel(const int*   __restrict__ tokens,
                 const int*   __restrict__ positions,
                 const float* __restrict__ emb,
                 const float* __restrict__ cP,
                 const float* __restrict__ M1,
                 const float* __restrict__ P1,
                 const float* __restrict__ g1, const float* __restrict__ b1,
                 const float* __restrict__ R1,
                 const float* __restrict__ M2,
                 const float* __restrict__ P2,
                 const float* __restrict__ g2, const float* __restrict__ b2,
                 float*       __restrict__ out)
{
    __shared__ float part[2048];          // per-stage partials [slice][b][i]
    __shared__ float xs[256];             // [b][j]  embeddings
    __shared__ float hs[256];             // [b][j]  layer-0 output
    __shared__ float ln1[512];            // [b][j]
    __shared__ float h1s[512];            // [b][j]
    __shared__ float ln2[512];            // [b][j]
    __shared__ float wsm[16], wsq[16];    // per-warp LN partial sums

    const int tid = threadIdx.x;
    const int s   = blockIdx.x;
    const float sf = (float)positions[s];

    // ---- gather embeddings ----
    if (tid < 256) {
        int b = tid >> 6, j = tid & 63;
        int tok = tokens[b * S_LEN + s];
        xs[tid] = emb[tok * 64 + j];
    }
    __syncthreads();

    // =====================================================================
    // Layer 0 (V=64): h[b][i] = sum_j cP[i][j] * cos(2pi s/(i*64+j+2)) * x[b][j]
    // 512 threads = 64 i x 8 j-slices of 8
    // =====================================================================
    {
        const int i = tid & 63, sl = tid >> 6;
        const int j0 = sl * 8;
        float a0 = 0.f, a1 = 0.f, a2 = 0.f, a3 = 0.f;
#pragma unroll
        for (int jj = 0; jj < 8; jj += 4) {
            int j = j0 + jj;
            float4 rp = *(const float4*)&g_rpV[i * 64 + j];
            float4 w  = *(const float4*)&cP[i * 64 + j];
            float p0 = w.x * pcos(sf, rp.x);
            float p1 = w.y * pcos(sf, rp.y);
            float p2 = w.z * pcos(sf, rp.z);
            float p3 = w.w * pcos(sf, rp.w);
            float4 v;
            v = *(const float4*)&xs[0 * 64 + j];
            a0 = fmaf(p0, v.x, fmaf(p1, v.y, fmaf(p2, v.z, fmaf(p3, v.w, a0))));
            v = *(const float4*)&xs[1 * 64 + j];
            a1 = fmaf(p0, v.x, fmaf(p1, v.y, fmaf(p2, v.z, fmaf(p3, v.w, a1))));
            v = *(const float4*)&xs[2 * 64 + j];
            a2 = fmaf(p0, v.x, fmaf(p1, v.y, fmaf(p2, v.z, fmaf(p3, v.w, a2))));
            v = *(const float4*)&xs[3 * 64 + j];
            a3 = fmaf(p0, v.x, fmaf(p1, v.y, fmaf(p2, v.z, fmaf(p3, v.w, a3))));
        }
        part[(sl * 4 + 0) * 64 + i] = a0;
        part[(sl * 4 + 1) * 64 + i] = a1;
        part[(sl * 4 + 2) * 64 + i] = a2;
        part[(sl * 4 + 3) * 64 + i] = a3;
    }
    __syncthreads();
    if (tid < 256) {
        int b = tid >> 6, i = tid & 63;
        float h = 0.f;
#pragma unroll
        for (int sl = 0; sl < 8; ++sl) h += part[(sl * 4 + b) * 64 + i];
        hs[b * 64 + i] = h;
    }
    __syncthreads();

    const int ii = tid & 127;   // output index (D)
    const int q  = tid >> 7;    // j-slice / batch selector
    const int bb = q;           // for reduce stages: b = tid>>7

    // =====================================================================
    // t1 = M1 @ h  (128x64)  : 128 i x 4 slices of 16 j
    // =====================================================================
    {
        float a0 = 0.f, a1 = 0.f, a2 = 0.f, a3 = 0.f;
        const int j0 = q * 16;
#pragma unroll
        for (int jj = 0; jj < 16; jj += 4) {
            int j = j0 + jj;
            float4 w = *(const float4*)&M1[ii * 64 + j];
            float4 v;
            v = *(const float4*)&hs[0 * 64 + j];
            a0 = fmaf(w.x, v.x, fmaf(w.y, v.y, fmaf(w.z, v.z, fmaf(w.w, v.w, a0))));
            v = *(const float4*)&hs[1 * 64 + j];
            a1 = fmaf(w.x, v.x, fmaf(w.y, v.y, fmaf(w.z, v.z, fmaf(w.w, v.w, a1))));
            v = *(const float4*)&hs[2 * 64 + j];
            a2 = fmaf(w.x, v.x, fmaf(w.y, v.y, fmaf(w.z, v.z, fmaf(w.w, v.w, a2))));
            v = *(const float4*)&hs[3 * 64 + j];
            a3 = fmaf(w.x, v.x, fmaf(w.y, v.y, fmaf(w.z, v.z, fmaf(w.w, v.w, a3))));
        }
        part[(q * 4 + 0) * 128 + ii] = a0;
        part[(q * 4 + 1) * 128 + ii] = a1;
        part[(q * 4 + 2) * 128 + ii] = a2;
        part[(q * 4 + 3) * 128 + ii] = a3;
    }
    __syncthreads();

    // ---- reduce t1 + LayerNorm 1 ----
    float t1v = part[(0 + bb) * 128 + ii] + part[(4 + bb) * 128 + ii]
              + part[(8 + bb) * 128 + ii] + part[(12 + bb) * 128 + ii];
    {
        float ws = warpsum(t1v), w2 = warpsum(t1v * t1v);
        int wid = tid >> 5;
        if ((tid & 31) == 0) { wsm[wid] = ws; wsq[wid] = w2; }
    }
    __syncthreads();
    {
        float mean = (wsm[bb * 4] + wsm[bb * 4 + 1] + wsm[bb * 4 + 2] + wsm[bb * 4 + 3]) * 0.0078125f;
        float ex2  = (wsq[bb * 4] + wsq[bb * 4 + 1] + wsq[bb * 4 + 2] + wsq[bb * 4 + 3]) * 0.0078125f;
        float rstd = rsqrtf(fmaf(-mean, mean, ex2) + 1e-5f);
        ln1[bb * 128 + ii] = (t1v - mean) * rstd * g1[ii] + b1[ii];
    }
    __syncthreads();

    // =====================================================================
    // h1 = posnk(ln1, P1, phiD) + R1 @ h
    // 128 i x 4 slices (32 j for P1-part, 16 j for R1-part)
    // =====================================================================
    {
        float a0 = 0.f, a1 = 0.f, a2 = 0.f, a3 = 0.f;
        const int j0 = q * 32;
#pragma unroll
        for (int jj = 0; jj < 32; jj += 4) {
            int j = j0 + jj;
            float4 rp = *(const float4*)&g_rpD[ii * 128 + j];
            float4 w  = *(const float4*)&P1[ii * 128 + j];
            float p0 = w.x * pcos(sf, rp.x);
            float p1 = w.y * pcos(sf, rp.y);
            float p2 = w.z * pcos(sf, rp.z);
            float p3 = w.w * pcos(sf, rp.w);
            float4 v;
            v = *(const float4*)&ln1[0 * 128 + j];
            a0 = fmaf(p0, v.x, fmaf(p1, v.y, fmaf(p2, v.z, fmaf(p3, v.w, a0))));
            v = *(const float4*)&ln1[1 * 128 + j];
            a1 = fmaf(p0, v.x, fmaf(p1, v.y, fmaf(p2, v.z, fmaf(p3, v.w, a1))));
            v = *(const float4*)&ln1[2 * 128 + j];
            a2 = fmaf(p0, v.x, fmaf(p1, v.y, fmaf(p2, v.z, fmaf(p3, v.w, a2))));
            v = *(const float4*)&ln1[3 * 128 + j];
            a3 = fmaf(p0, v.x, fmaf(p1, v.y, fmaf(p2, v.z, fmaf(p3, v.w, a3))));
        }
        const int k0 = q * 16;
#pragma unroll
        for (int jj = 0; jj < 16; jj += 4) {
            int j = k0 + jj;
            float4 w = *(const float4*)&R1[ii * 64 + j];
            float4 v;
            v = *(const float4*)&hs[0 * 64 + j];
            a0 = fmaf(w.x, v.x, fmaf(w.y, v.y, fmaf(w.z, v.z, fmaf(w.w, v.w, a0))));
            v = *(const float4*)&hs[1 * 64 + j];
            a1 = fmaf(w.x, v.x, fmaf(w.y, v.y, fmaf(w.z, v.z, fmaf(w.w, v.w, a1))));
            v = *(const float4*)&hs[2 * 64 + j];
            a2 = fmaf(w.x, v.x, fmaf(w.y, v.y, fmaf(w.z, v.z, fmaf(w.w, v.w, a2))));
            v = *(const float4*)&hs[3 * 64 + j];
            a3 = fmaf(w.x, v.x, fmaf(w.y, v.y, fmaf(w.z, v.z, fmaf(w.w, v.w, a3))));
        }
        part[(q * 4 + 0) * 128 + ii] = a0;
        part[(q * 4 + 1) * 128 + ii] = a1;
        part[(q * 4 + 2) * 128 + ii] = a2;
        part[(q * 4 + 3) * 128 + ii] = a3;
    }
    __syncthreads();
    {
        float v = part[(0 + bb) * 128 + ii] + part[(4 + bb) * 128 + ii]
                + part[(8 + bb) * 128 + ii] + part[(12 + bb) * 128 + ii];
        h1s[bb * 128 + ii] = v;
    }
    __syncthreads();

    // =====================================================================
    // t2 = M2 @ h1 (128x128) : 128 i x 4 slices of 32 j
    // =====================================================================
    {
        float a0 = 0.f, a1 = 0.f, a2 = 0.f, a3 = 0.f;
        const int j0 = q * 32;
#pragma unroll
        for (int jj = 0; jj < 32; jj += 4) {
            int j = j0 + jj;
            float4 w = *(const float4*)&M2[ii * 128 + j];
            float4 v;
            v = *(const float4*)&h1s[0 * 128 + j];
            a0 = fmaf(w.x, v.x, fmaf(w.y, v.y, fmaf(w.z, v.z, fmaf(w.w, v.w, a0))));
            v = *(const float4*)&h1s[1 * 128 + j];
            a1 = fmaf(w.x, v.x, fmaf(w.y, v.y, fmaf(w.z, v.z, fmaf(w.w, v.w, a1))));
            v = *(const float4*)&h1s[2 * 128 + j];
            a2 = fmaf(w.x, v.x, fmaf(w.y, v.y, fmaf(w.z, v.z, fmaf(w.w, v.w, a2))));
            v = *(const float4*)&h1s[3 * 128 + j];
            a3 = fmaf(w.x, v.x, fmaf(w.y, v.y, fmaf(w.z, v.z, fmaf(w.w, v.w, a3))));
        }
        part[(q * 4 + 0) * 128 + ii] = a0;
        part[(q * 4 + 1) * 128 + ii] = a1;
        part[(q * 4 + 2) * 128 + ii] = a2;
        part[(q * 4 + 3) * 128 + ii] = a3;
    }
    __syncthreads();

    // ---- reduce t2 + LayerNorm 2 (keep t2v in register for residual) ----
    float t2v = part[(0 + bb) * 128 + ii] + part[(4 + bb) * 128 + ii]
              + part[(8 + bb) * 128 + ii] + part[(12 + bb) * 128 + ii];
    {
        float ws = warpsum(t2v), w2 = warpsum(t2v * t2v);
        int wid = tid >> 5;
        if ((tid & 31) == 0) { wsm[wid] = ws; wsq[wid] = w2; }
    }
    __syncthreads();
    {
        float mean = (wsm[bb * 4] + wsm[bb * 4 + 1] + wsm[bb * 4 + 2] + wsm[bb * 4 + 3]) * 0.0078125f;
        float ex2  = (wsq[bb * 4] + wsq[bb * 4 + 1] + wsq[bb * 4 + 2] + wsq[bb * 4 + 3]) * 0.0078125f;
        float rstd = rsqrtf(fmaf(-mean, mean, ex2) + 1e-5f);
        ln2[bb * 128 + ii] = (t2v - mean) * rstd * g2[ii] + b2[ii];
    }
    __syncthreads();

    // =====================================================================
    // out = posnk(ln2, P2, phiD) + t2
    // =====================================================================
    {
        float a0 = 0.f, a1 = 0.f, a2 = 0.f, a3 = 0.f;
        const int j0 = q * 32;
#pragma unroll
        for (int jj = 0; jj < 32; jj += 4) {
            int j = j0 + jj;
            float4 rp = *(const float4*)&g_rpD[ii * 128 + j];
            float4 w  = *(const float4*)&P2[ii * 128 + j];
            float p0 = w.x * pcos(sf, rp.x);
            float p1 = w.y * pcos(sf, rp.y);
            float p2 = w.z * pcos(sf, rp.z);
            float p3 = w.w * pcos(sf, rp.w);
            float4 v;
            v = *(const float4*)&ln2[0 * 128 + j];
            a0 = fmaf(p0, v.x, fmaf(p1, v.y, fmaf(p2, v.z, fmaf(p3, v.w, a0))));
            v = *(const float4*)&ln2[1 * 128 + j];
            a1 = fmaf(p0, v.x, fmaf(p1, v.y, fmaf(p2, v.z, fmaf(p3, v.w, a1))));
            v = *(const float4*)&ln2[2 * 128 + j];
            a2 = fmaf(p0, v.x, fmaf(p1, v.y, fmaf(p2, v.z, fmaf(p3, v.w, a2))));
            v = *(const float4*)&ln2[3 * 128 + j];
            a3 = fmaf(p0, v.x, fmaf(p1, v.y, fmaf(p2, v.z, fmaf(p3, v.w, a3))));
        }
        part[(q * 4 + 0) * 128 + ii] = a0;
        part[(q * 4 + 1) * 128 + ii] = a1;
        part[(q * 4 + 2) * 128 + ii] = a2;
        part[(q * 4 + 3) * 128 + ii] = a3;
    }
    __syncthreads();
    {
        float o = part[(0 + bb) * 128 + ii] + part[(4 + bb) * 128 + ii]
                + part[(8 + bb) * 128 + ii] + part[(12 + bb) * 128 + ii] + t2v;
        out[((size_t)bb * S_LEN + s) * 128 + ii] = o;
    }
}

extern "C" void kernel_launch(void* const* d_in, const int* in_sizes, int n_in,
                              void* d_out, int out_size)
{
    const int*   tokens    = (const int*)  d_in[0];
    const int*   positions = (const int*)  d_in[1];
    const float* emb       = (const float*)d_in[2];
    const float* char_P    = (const float*)d_in[3];
    const float* M1        = (const float*)d_in[4];
    const float* P1        = (const float*)d_in[5];
    const float* g1        = (const float*)d_in[6];
    const float* b1        = (const float*)d_in[7];
    const float* R1        = (const float*)d_in[8];
    const float* M2        = (const float*)d_in[9];
    const float* P2        = (const float*)d_in[10];
    const float* g2        = (const float*)d_in[11];
    const float* b2        = (const float*)d_in[12];
    float* out = (float*)d_out;

    prep_kernel<<<32, 512>>>();
    hier_kernel<<<S_LEN, 512>>>(tokens, positions, emb, char_P, M1, P1,
                                g1, b1, R1, M2, P2, g2, b2, out);
}

// round 3
// speedup vs baseline: 1.9481x; 1.9481x over previous
#include <cuda_runtime.h>

#define S_LEN 4096
#define TWO_PI_F 6.28318530717958647692f

// Transposed weights [j][i] + exact reciprocal-period tables (linear [j][i] order)
__device__ float g_cPt[64 * 64];
__device__ float g_M1t[64 * 128];
__device__ float g_R1t[64 * 128];
__device__ float g_M2t[128 * 128];
__device__ float g_P1t[128 * 128];
__device__ float g_P2t[128 * 128];
__device__ float g_rpDt[128 * 128];  // rpDt[j*128+i] = 1/(i*128+j+2), exact div
__device__ float g_rpVt[64 * 64];    // rpVt[j*64+i]  = 1/(i*64+j+2)

__global__ void prep_kernel(
    const float* __restrict__ cP, const float* __restrict__ M1,
    const float* __restrict__ R1, const float* __restrict__ M2,
    const float* __restrict__ P1, const float* __restrict__ P2)
{
    int t = blockIdx.x * blockDim.x + threadIdx.x;
    if (t < 16384) {
        int i = t >> 7, j = t & 127;
        g_M2t[j * 128 + i] = M2[t];
        g_P1t[j * 128 + i] = P1[t];
        g_P2t[j * 128 + i] = P2[t];
        g_rpDt[t] = 1.0f / (float)((t & 127) * 128 + (t >> 7) + 2);
    }
    if (t < 8192) {
        int i = t >> 6, j = t & 63;
        g_M1t[j * 128 + i] = M1[t];
        g_R1t[j * 128 + i] = R1[t];
    }
    if (t < 4096) {
        int i = t >> 6, j = t & 63;
        g_cPt[j * 64 + i] = cP[t];
        g_rpVt[t] = 1.0f / (float)((t & 63) * 64 + (t >> 6) + 2);
    }
}

// cos(2*pi*s/p) via s*rp; exact fractional part with fma, __cosf on [-pi,pi]
__device__ __forceinline__ float pcos(float sf, float rp)
{
    float f = sf * rp;
    float n = rintf(f);
    float r = fmaf(sf, rp, -n);
    return __cosf(TWO_PI_F * r);
}

__device__ __forceinline__ float warpsum(float v)
{
#pragma unroll
    for (int o = 16; o > 0; o >>= 1) v += __shfl_xor_sync(0xffffffffu, v, o);
    return v;
}

// dynamic smem layout (floats)
#define OFF_PHID 0          // 16384
#define OFF_PART 16384      // 2048
#define OFF_XS   18432      // 256
#define OFF_HS   18688      // 256
#define OFF_LN1  18944      // 512
#define OFF_H1S  19456      // 512
#define OFF_LN2  19968      // 512
#define OFF_WSM  20480      // 16
#define OFF_WSQ  20496      // 16
#define SM_FLOATS 20512
#define SMEM_BYTES (SM_FLOATS * 4)

__global__ __launch_bounds__(512, 2)
void hier_kernel(const int*   __restrict__ tokens,
                 const int*   __restrict__ positions,
                 const float* __restrict__ emb,
                 const float* __restrict__ g1, const float* __restrict__ b1,
                 const float* __restrict__ g2, const float* __restrict__ b2,
                 float*       __restrict__ out)
{
    extern __shared__ __align__(16) float sm[];
    float* phiD = sm + OFF_PHID;
    float* part = sm + OFF_PART;
    float* xs   = sm + OFF_XS;
    float* hs   = sm + OFF_HS;
    float* ln1  = sm + OFF_LN1;
    float* h1s  = sm + OFF_H1S;
    float* ln2  = sm + OFF_LN2;
    float* wsm  = sm + OFF_WSM;
    float* wsq  = sm + OFF_WSQ;

    const int tid = threadIdx.x;
    const int s   = blockIdx.x;
    const float sf = (float)positions[s];

    // ---- build phiD[j][i] (16384 entries), coalesced float4 ----
#pragma unroll
    for (int n = 0; n < 8; ++n) {
        int k = n * 2048 + tid * 4;
        float4 rp = *(const float4*)&g_rpDt[k];
        float4 ph;
        ph.x = pcos(sf, rp.x); ph.y = pcos(sf, rp.y);
        ph.z = pcos(sf, rp.z); ph.w = pcos(sf, rp.w);
        *(float4*)&phiD[k] = ph;
    }

    // ---- gather embeddings xs[b][j] ----
    if (tid < 256) {
        int b = tid >> 6, j = tid & 63;
        int tok = tokens[b * S_LEN + s];
        xs[tid] = emb[tok * 64 + j];
    }
    __syncthreads();

    // =====================================================================
    // Layer 0 (V=64): 64 i x 8 j-slices of 8; phiV inline
    // =====================================================================
    {
        const int i = tid & 63, sl = tid >> 6;
        float a0 = 0.f, a1 = 0.f, a2 = 0.f, a3 = 0.f;
#pragma unroll
        for (int jj = 0; jj < 8; ++jj) {
            int j = sl * 8 + jj;
            float p = g_cPt[j * 64 + i] * pcos(sf, g_rpVt[j * 64 + i]);
            a0 = fmaf(p, xs[j],       a0);
            a1 = fmaf(p, xs[64 + j],  a1);
            a2 = fmaf(p, xs[128 + j], a2);
            a3 = fmaf(p, xs[192 + j], a3);
        }
        part[sl * 256 + i]       = a0;
        part[sl * 256 + 64 + i]  = a1;
        part[sl * 256 + 128 + i] = a2;
        part[sl * 256 + 192 + i] = a3;
    }
    __syncthreads();
    if (tid < 256) {
        float h = 0.f;
#pragma unroll
        for (int sl = 0; sl < 8; ++sl) h += part[sl * 256 + tid];
        hs[tid] = h;
    }
    __syncthreads();

    // mapping for D stages: b-group of 128 threads; within it 4 warps = 4 j-slices
    const int b    = tid >> 7;        // 0..3
    const int t128 = tid & 127;
    const int i4   = (t128 & 31) * 4; // float4 i-base, lane-consecutive
    const int js   = t128 >> 5;       // 0..3 j-slice
    const int ii   = t128;            // reduce-stage i

#define FMA4(acc, w, p)                        \
    acc.x = fmaf((w).x, (p), acc.x);           \
    acc.y = fmaf((w).y, (p), acc.y);           \
    acc.z = fmaf((w).z, (p), acc.z);           \
    acc.w = fmaf((w).w, (p), acc.w);

#define FMA4P(acc, w, ph, a)                               \
    acc.x = fmaf((w).x * (ph).x, (a), acc.x);              \
    acc.y = fmaf((w).y * (ph).y, (a), acc.y);              \
    acc.z = fmaf((w).z * (ph).z, (a), acc.z);              \
    acc.w = fmaf((w).w * (ph).w, (a), acc.w);

    // =====================================================================
    // t1 = M1 @ h : j-slice of 16 from V=64
    // =====================================================================
    {
        float4 acc = make_float4(0.f, 0.f, 0.f, 0.f);
        const float* hb = hs + b * 64;
#pragma unroll
        for (int j4 = 0; j4 < 4; ++j4) {
            int j = js * 16 + j4 * 4;
            float4 act = *(const float4*)&hb[j];
            float4 w;
            w = *(const float4*)&g_M1t[(j + 0) * 128 + i4]; FMA4(acc, w, act.x);
            w = *(const float4*)&g_M1t[(j + 1) * 128 + i4]; FMA4(acc, w, act.y);
            w = *(const float4*)&g_M1t[(j + 2) * 128 + i4]; FMA4(acc, w, act.z);
            w = *(const float4*)&g_M1t[(j + 3) * 128 + i4]; FMA4(acc, w, act.w);
        }
        *(float4*)&part[js * 512 + b * 128 + i4] = acc;
    }
    __syncthreads();

    // ---- reduce t1 + LayerNorm 1 ----
    float t1v = part[0 * 512 + b * 128 + ii] + part[1 * 512 + b * 128 + ii]
              + part[2 * 512 + b * 128 + ii] + part[3 * 512 + b * 128 + ii];
    {
        float ws = warpsum(t1v), w2 = warpsum(t1v * t1v);
        if ((tid & 31) == 0) { wsm[tid >> 5] = ws; wsq[tid >> 5] = w2; }
    }
    __syncthreads();
    {
        float mean = (wsm[b * 4] + wsm[b * 4 + 1] + wsm[b * 4 + 2] + wsm[b * 4 + 3]) * 0.0078125f;
        float ex2  = (wsq[b * 4] + wsq[b * 4 + 1] + wsq[b * 4 + 2] + wsq[b * 4 + 3]) * 0.0078125f;
        float rstd = rsqrtf(fmaf(-mean, mean, ex2) + 1e-5f);
        ln1[b * 128 + ii] = (t1v - mean) * rstd * g1[ii] + b1[ii];
    }
    __syncthreads();

    // =====================================================================
    // h1 = posnk(ln1, P1, phiD) + R1 @ h : 32 j (P) + 16 j (R) per slice
    // =====================================================================
    {
        float4 acc = make_float4(0.f, 0.f, 0.f, 0.f);
        const float* lb = ln1 + b * 128;
#pragma unroll
        for (int j4 = 0; j4 < 8; ++j4) {
            int j = js * 32 + j4 * 4;
            float4 act = *(const float4*)&lb[j];
            float4 w, ph;
            w  = *(const float4*)&g_P1t[(j + 0) * 128 + i4];
            ph = *(const float4*)&phiD [(j + 0) * 128 + i4]; FMA4P(acc, w, ph, act.x);
            w  = *(const float4*)&g_P1t[(j + 1) * 128 + i4];
            ph = *(const float4*)&phiD [(j + 1) * 128 + i4]; FMA4P(acc, w, ph, act.y);
            w  = *(const float4*)&g_P1t[(j + 2) * 128 + i4];
            ph = *(const float4*)&phiD [(j + 2) * 128 + i4]; FMA4P(acc, w, ph, act.z);
            w  = *(const float4*)&g_P1t[(j + 3) * 128 + i4];
            ph = *(const float4*)&phiD [(j + 3) * 128 + i4]; FMA4P(acc, w, ph, act.w);
        }
        const float* hb = hs + b * 64;
#pragma unroll
        for (int j4 = 0; j4 < 4; ++j4) {
            int j = js * 16 + j4 * 4;
            float4 act = *(const float4*)&hb[j];
            float4 w;
            w = *(const float4*)&g_R1t[(j + 0) * 128 + i4]; FMA4(acc, w, act.x);
            w = *(const float4*)&g_R1t[(j + 1) * 128 + i4]; FMA4(acc, w, act.y);
            w = *(const float4*)&g_R1t[(j + 2) * 128 + i4]; FMA4(acc, w, act.z);
            w = *(const float4*)&g_R1t[(j + 3) * 128 + i4]; FMA4(acc, w, act.w);
        }
        *(float4*)&part[js * 512 + b * 128 + i4] = acc;
    }
    __syncthreads();
    h1s[b * 128 + ii] = part[0 * 512 + b * 128 + ii] + part[1 * 512 + b * 128 + ii]
                      + part[2 * 512 + b * 128 + ii] + part[3 * 512 + b * 128 + ii];
    __syncthreads();

    // =====================================================================
    // t2 = M2 @ h1 : 32 j per slice
    // =====================================================================
    {
        float4 acc = make_float4(0.f, 0.f, 0.f, 0.f);
        const float* hb = h1s + b * 128;
#pragma unroll
        for (int j4 = 0; j4 < 8; ++j4) {
            int j = js * 32 + j4 * 4;
            float4 act = *(const float4*)&hb[j];
            float4 w;
            w = *(const float4*)&g_M2t[(j + 0) * 128 + i4]; FMA4(acc, w, act.x);
            w = *(const float4*)&g_M2t[(j + 1) * 128 + i4]; FMA4(acc, w, act.y);
            w = *(const float4*)&g_M2t[(j + 2) * 128 + i4]; FMA4(acc, w, act.z);
            w = *(const float4*)&g_M2t[(j + 3) * 128 + i4]; FMA4(acc, w, act.w);
        }
        *(float4*)&part[js * 512 + b * 128 + i4] = acc;
    }
    __syncthreads();

    // ---- reduce t2 + LayerNorm 2 (t2v kept in register for residual) ----
    float t2v = part[0 * 512 + b * 128 + ii] + part[1 * 512 + b * 128 + ii]
              + part[2 * 512 + b * 128 + ii] + part[3 * 512 + b * 128 + ii];
    {
        float ws = warpsum(t2v), w2 = warpsum(t2v * t2v);
        if ((tid & 31) == 0) { wsm[tid >> 5] = ws; wsq[tid >> 5] = w2; }
    }
    __syncthreads();
    {
        float mean = (wsm[b * 4] + wsm[b * 4 + 1] + wsm[b * 4 + 2] + wsm[b * 4 + 3]) * 0.0078125f;
        float ex2  = (wsq[b * 4] + wsq[b * 4 + 1] + wsq[b * 4 + 2] + wsq[b * 4 + 3]) * 0.0078125f;
        float rstd = rsqrtf(fmaf(-mean, mean, ex2) + 1e-5f);
        ln2[b * 128 + ii] = (t2v - mean) * rstd * g2[ii] + b2[ii];
    }
    __syncthreads();

    // =====================================================================
    // out = posnk(ln2, P2, phiD) + t2
    // =====================================================================
    {
        float4 acc = make_float4(0.f, 0.f, 0.f, 0.f);
        const float* lb = ln2 + b * 128;
#pragma unroll
        for (int j4 = 0; j4 < 8; ++j4) {
            int j = js * 32 + j4 * 4;
            float4 act = *(const float4*)&lb[j];
            float4 w, ph;
            w  = *(const float4*)&g_P2t[(j + 0) * 128 + i4];
            ph = *(const float4*)&phiD [(j + 0) * 128 + i4]; FMA4P(acc, w, ph, act.x);
            w  = *(const float4*)&g_P2t[(j + 1) * 128 + i4];
            ph = *(const float4*)&phiD [(j + 1) * 128 + i4]; FMA4P(acc, w, ph, act.y);
            w  = *(const float4*)&g_P2t[(j + 2) * 128 + i4];
            ph = *(const float4*)&phiD [(j + 2) * 128 + i4]; FMA4P(acc, w, ph, act.z);
            w  = *(const float4*)&g_P2t[(j + 3) * 128 + i4];
            ph = *(const float4*)&phiD [(j + 3) * 128 + i4]; FMA4P(acc, w, ph, act.w);
        }
        *(float4*)&part[js * 512 + b * 128 + i4] = acc;
    }
    __syncthreads();
    {
        float o = part[0 * 512 + b * 128 + ii] + part[1 * 512 + b * 128 + ii]
                + part[2 * 512 + b * 128 + ii] + part[3 * 512 + b * 128 + ii] + t2v;
        out[((size_t)b * S_LEN + s) * 128 + ii] = o;
    }
}

extern "C" void kernel_launch(void* const* d_in, const int* in_sizes, int n_in,
                              void* d_out, int out_size)
{
    const int*   tokens    = (const int*)  d_in[0];
    const int*   positions = (const int*)  d_in[1];
    const float* emb       = (const float*)d_in[2];
    const float* char_P    = (const float*)d_in[3];
    const float* M1        = (const float*)d_in[4];
    const float* P1        = (const float*)d_in[5];
    const float* g1        = (const float*)d_in[6];
    const float* b1        = (const float*)d_in[7];
    const float* R1        = (const float*)d_in[8];
    const float* M2        = (const float*)d_in[9];
    const float* P2        = (const float*)d_in[10];
    const float* g2        = (const float*)d_in[11];
    const float* b2        = (const float*)d_in[12];
    float* out = (float*)d_out;

    cudaFuncSetAttribute(hier_kernel,
                         cudaFuncAttributeMaxDynamicSharedMemorySize, SMEM_BYTES);

    prep_kernel<<<32, 512>>>(char_P, M1, R1, M2, P1, P2);
    hier_kernel<<<S_LEN, 512, SMEM_BYTES>>>(tokens, positions, emb,
                                            g1, b1, g2, b2, out);
}

// round 5
// speedup vs baseline: 2.8638x; 1.4701x over previous
#include <cuda_runtime.h>

#define S_LEN 4096
#define TWO_PI_F 6.28318530717958647692f

// Transposed weights [j][i] + exact reciprocal-period tables (linear [j][i] order)
__device__ float g_cPt[64 * 64];
__device__ float g_M1t[64 * 128];
__device__ float g_R1t[64 * 128];
__device__ float g_M2t[128 * 128];
__device__ float g_P1t[128 * 128];
__device__ float g_P2t[128 * 128];
__device__ float g_rpDt[128 * 128];  // rpDt[j*128+i] = 1/(i*128+j+2)
__device__ float g_rpVt[64 * 64];    // rpVt[j*64+i]  = 1/(i*64+j+2)

__global__ void prep_kernel(
    const float* __restrict__ cP, const float* __restrict__ M1,
    const float* __restrict__ R1, const float* __restrict__ M2,
    const float* __restrict__ P1, const float* __restrict__ P2)
{
    int t = blockIdx.x * blockDim.x + threadIdx.x;
    if (t < 16384) {
        int i = t >> 7, j = t & 127;
        g_M2t[j * 128 + i] = M2[t];
        g_P1t[j * 128 + i] = P1[t];
        g_P2t[j * 128 + i] = P2[t];
        g_rpDt[t] = 1.0f / (float)((t & 127) * 128 + (t >> 7) + 2);
    }
    if (t < 8192) {
        int i = t >> 6, j = t & 63;
        g_M1t[j * 128 + i] = M1[t];
        g_R1t[j * 128 + i] = R1[t];
    }
    if (t < 4096) {
        int i = t >> 6, j = t & 63;
        g_cPt[j * 64 + i] = cP[t];
        g_rpVt[t] = 1.0f / (float)((t & 63) * 64 + (t >> 6) + 2);
    }
}

__device__ __forceinline__ float pcos(float sf, float rp)
{
    float f = sf * rp;
    float n = rintf(f);
    float r = fmaf(sf, rp, -n);
    return __cosf(TWO_PI_F * r);
}

__device__ __forceinline__ float warpsum(float v)
{
#pragma unroll
    for (int o = 16; o > 0; o >>= 1) v += __shfl_xor_sync(0xffffffffu, v, o);
    return v;
}

// dynamic smem layout (floats)
#define OFF_PHID 0          // 16384
#define OFF_PART 16384      // 8192
#define OFF_XS   24576      // 256
#define OFF_HS   24832      // 256
#define OFF_LN1  25088      // 512
#define OFF_H1S  25600      // 512
#define OFF_LN2  26112      // 512
#define OFF_WSM  26624      // 16
#define OFF_WSQ  26640      // 16
#define SM_FLOATS 26656
#define SMEM_BYTES (SM_FLOATS * 4)

#define FMA4(acc, w, a) {                      \
    acc.x = fmaf((w).x, (a), acc.x);           \
    acc.y = fmaf((w).y, (a), acc.y);           \
    acc.z = fmaf((w).z, (a), acc.z);           \
    acc.w = fmaf((w).w, (a), acc.w); }

// plain weight step: one j, all 4 batches, 4 i
#define WSTEP(WARR, J, COMP) {                                      \
    float4 w = *(const float4*)&WARR[(size_t)(J) * 128 + i4];       \
    FMA4(acc0, w, A0.COMP); FMA4(acc1, w, A1.COMP);                 \
    FMA4(acc2, w, A2.COMP); FMA4(acc3, w, A3.COMP); }

// phase-modulated weight step
#define PSTEP(WARR, J, COMP) {                                      \
    float4 w  = *(const float4*)&WARR[(size_t)(J) * 128 + i4];      \
    float4 ph = *(const float4*)&phiD[(J) * 128 + i4];              \
    w.x *= ph.x; w.y *= ph.y; w.z *= ph.z; w.w *= ph.w;             \
    FMA4(acc0, w, A0.COMP); FMA4(acc1, w, A1.COMP);                 \
    FMA4(acc2, w, A2.COMP); FMA4(acc3, w, A3.COMP); }

#define LOADA(SRC, STRIDE, J)                            \
    A0 = *(const float4*)&(SRC)[0 * (STRIDE) + (J)];     \
    A1 = *(const float4*)&(SRC)[1 * (STRIDE) + (J)];     \
    A2 = *(const float4*)&(SRC)[2 * (STRIDE) + (J)];     \
    A3 = *(const float4*)&(SRC)[3 * (STRIDE) + (J)];

#define STOREP()                                          \
    *(float4*)&part[(js * 4 + 0) * 128 + i4] = acc0;      \
    *(float4*)&part[(js * 4 + 1) * 128 + i4] = acc1;      \
    *(float4*)&part[(js * 4 + 2) * 128 + i4] = acc2;      \
    *(float4*)&part[(js * 4 + 3) * 128 + i4] = acc3;

__global__ __launch_bounds__(512, 2)
void hier_kernel(const int*   __restrict__ tokens,
                 const int*   __restrict__ positions,
                 const float* __restrict__ emb,
                 const float* __restrict__ g1, const float* __restrict__ b1,
                 const float* __restrict__ g2, const float* __restrict__ b2,
                 float*       __restrict__ out)
{
    extern __shared__ __align__(16) float sm[];
    float* phiD = sm + OFF_PHID;
    float* part = sm + OFF_PART;
    float* xs   = sm + OFF_XS;
    float* hs   = sm + OFF_HS;
    float* ln1  = sm + OFF_LN1;
    float* h1s  = sm + OFF_H1S;
    float* ln2  = sm + OFF_LN2;
    float* wsm  = sm + OFF_WSM;
    float* wsq  = sm + OFF_WSQ;

    const int tid = threadIdx.x;
    const int s   = blockIdx.x;
    const float sf = (float)positions[s];

    // ---- build phiD[j][i] once per CTA ----
#pragma unroll
    for (int n = 0; n < 8; ++n) {
        int k = n * 2048 + tid * 4;
        float4 rp = *(const float4*)&g_rpDt[k];
        float4 ph;
        ph.x = pcos(sf, rp.x); ph.y = pcos(sf, rp.y);
        ph.z = pcos(sf, rp.z); ph.w = pcos(sf, rp.w);
        *(float4*)&phiD[k] = ph;
    }

    // ---- gather embeddings xs[b][j] ----
    if (tid < 256) {
        int b0 = tid >> 6, j0 = tid & 63;
        int tok = tokens[b0 * S_LEN + s];
        xs[tid] = emb[tok * 64 + j0];
    }
    __syncthreads();

    // =====================================================================
    // Layer 0 (V=64): thread = (i, slice of 8 j), batch in accumulators
    // =====================================================================
    {
        const int i = tid & 63, sl = tid >> 6;
        float a0 = 0.f, a1 = 0.f, a2 = 0.f, a3 = 0.f;
#pragma unroll
        for (int jj = 0; jj < 8; ++jj) {
            int j = sl * 8 + jj;
            float p = g_cPt[j * 64 + i] * pcos(sf, g_rpVt[j * 64 + i]);
            a0 = fmaf(p, xs[j],       a0);
            a1 = fmaf(p, xs[64 + j],  a1);
            a2 = fmaf(p, xs[128 + j], a2);
            a3 = fmaf(p, xs[192 + j], a3);
        }
        part[sl * 256 + i]       = a0;
        part[sl * 256 + 64 + i]  = a1;
        part[sl * 256 + 128 + i] = a2;
        part[sl * 256 + 192 + i] = a3;
    }
    __syncthreads();
    if (tid < 256) {
        float h = 0.f;
#pragma unroll
        for (int sl = 0; sl < 8; ++sl) h += part[sl * 256 + tid];
        hs[tid] = h;
    }
    __syncthreads();

    // D-stage mapping: warp = j-slice, lanes cover all 128 i as float4
    const int js = tid >> 5;          // 0..15
    const int i4 = (tid & 31) * 4;    // float4 i-base
    const int b  = tid >> 7;          // reduce/LN mapping
    const int ii = tid & 127;

    // =====================================================================
    // t1 = M1 @ h : 64 j, slice of 4
    // =====================================================================
    {
        float4 acc0 = {0,0,0,0}, acc1 = {0,0,0,0}, acc2 = {0,0,0,0}, acc3 = {0,0,0,0};
        float4 A0, A1, A2, A3;
        const int j0 = js * 4;
        LOADA(hs, 64, j0);
        WSTEP(g_M1t, j0 + 0, x); WSTEP(g_M1t, j0 + 1, y);
        WSTEP(g_M1t, j0 + 2, z); WSTEP(g_M1t, j0 + 3, w);
        STOREP();
    }
    __syncthreads();

    // ---- reduce t1 + LayerNorm 1 ----
    float t1v = 0.f;
#pragma unroll
    for (int k = 0; k < 16; ++k) t1v += part[(k * 4 + b) * 128 + ii];
    {
        float ws = warpsum(t1v), w2 = warpsum(t1v * t1v);
        if ((tid & 31) == 0) { wsm[js] = ws; wsq[js] = w2; }
    }
    __syncthreads();
    {
        float mean = (wsm[b * 4] + wsm[b * 4 + 1] + wsm[b * 4 + 2] + wsm[b * 4 + 3]) * 0.0078125f;
        float ex2  = (wsq[b * 4] + wsq[b * 4 + 1] + wsq[b * 4 + 2] + wsq[b * 4 + 3]) * 0.0078125f;
        float rstd = rsqrtf(fmaf(-mean, mean, ex2) + 1e-5f);
        ln1[b * 128 + ii] = (t1v - mean) * rstd * g1[ii] + b1[ii];
    }
    __syncthreads();

    // =====================================================================
    // h1 = posnk(ln1, P1, phiD) + R1 @ h : 8 j (P) + 4 j (R) per slice
    // =====================================================================
    {
        float4 acc0 = {0,0,0,0}, acc1 = {0,0,0,0}, acc2 = {0,0,0,0}, acc3 = {0,0,0,0};
        float4 A0, A1, A2, A3;
        const int j0 = js * 8;
        LOADA(ln1, 128, j0);
        PSTEP(g_P1t, j0 + 0, x); PSTEP(g_P1t, j0 + 1, y);
        PSTEP(g_P1t, j0 + 2, z); PSTEP(g_P1t, j0 + 3, w);
        LOADA(ln1, 128, j0 + 4);
        PSTEP(g_P1t, j0 + 4, x); PSTEP(g_P1t, j0 + 5, y);
        PSTEP(g_P1t, j0 + 6, z); PSTEP(g_P1t, j0 + 7, w);
        const int jr = js * 4;
        LOADA(hs, 64, jr);
        WSTEP(g_R1t, jr + 0, x); WSTEP(g_R1t, jr + 1, y);
        WSTEP(g_R1t, jr + 2, z); WSTEP(g_R1t, jr + 3, w);
        STOREP();
    }
    __syncthreads();
    {
        float v = 0.f;
#pragma unroll
        for (int k = 0; k < 16; ++k) v += part[(k * 4 + b) * 128 + ii];
        h1s[b * 128 + ii] = v;
    }
    __syncthreads();

    // =====================================================================
    // t2 = M2 @ h1 : 8 j per slice
    // =====================================================================
    {
        float4 acc0 = {0,0,0,0}, acc1 = {0,0,0,0}, acc2 = {0,0,0,0}, acc3 = {0,0,0,0};
        float4 A0, A1, A2, A3;
        const int j0 = js * 8;
        LOADA(h1s, 128, j0);
        WSTEP(g_M2t, j0 + 0, x); WSTEP(g_M2t, j0 + 1, y);
        WSTEP(g_M2t, j0 + 2, z); WSTEP(g_M2t, j0 + 3, w);
        LOADA(h1s, 128, j0 + 4);
        WSTEP(g_M2t, j0 + 4, x); WSTEP(g_M2t, j0 + 5, y);
        WSTEP(g_M2t, j0 + 6, z); WSTEP(g_M2t, j0 + 7, w);
        STOREP();
    }
    __syncthreads();

    // ---- reduce t2 + LayerNorm 2 (t2v kept for residual) ----
    float t2v = 0.f;
#pragma unroll
    for (int k = 0; k < 16; ++k) t2v += part[(k * 4 + b) * 128 + ii];
    {
        float ws = warpsum(t2v), w2 = warpsum(t2v * t2v);
        if ((tid & 31) == 0) { wsm[js] = ws; wsq[js] = w2; }
    }
    __syncthreads();
    {
        float mean = (wsm[b * 4] + wsm[b * 4 + 1] + wsm[b * 4 + 2] + wsm[b * 4 + 3]) * 0.0078125f;
        float ex2  = (wsq[b * 4] + wsq[b * 4 + 1] + wsq[b * 4 + 2] + wsq[b * 4 + 3]) * 0.0078125f;
        float rstd = rsqrtf(fmaf(-mean, mean, ex2) + 1e-5f);
        ln2[b * 128 + ii] = (t2v - mean) * rstd * g2[ii] + b2[ii];
    }
    __syncthreads();

    // =====================================================================
    // out = posnk(ln2, P2, phiD) + t2
    // =====================================================================
    {
        float4 acc0 = {0,0,0,0}, acc1 = {0,0,0,0}, acc2 = {0,0,0,0}, acc3 = {0,0,0,0};
        float4 A0, A1, A2, A3;
        const int j0 = js * 8;
        LOADA(ln2, 128, j0);
        PSTEP(g_P2t, j0 + 0, x); PSTEP(g_P2t, j0 + 1, y);
        PSTEP(g_P2t, j0 + 2, z); PSTEP(g_P2t, j0 + 3, w);
        LOADA(ln2, 128, j0 + 4);
        PSTEP(g_P2t, j0 + 4, x); PSTEP(g_P2t, j0 + 5, y);
        PSTEP(g_P2t, j0 + 6, z); PSTEP(g_P2t, j0 + 7, w);
        STOREP();
    }
    __syncthreads();
    {
        float o = t2v;
#pragma unroll
        for (int k = 0; k < 16; ++k) o += part[(k * 4 + b) * 128 + ii];
        out[((size_t)b * S_LEN + s) * 128 + ii] = o;
    }
}

extern "C" void kernel_launch(void* const* d_in, const int* in_sizes, int n_in,
                              void* d_out, int out_size)
{
    const int*   tokens    = (const int*)  d_in[0];
    const int*   positions = (const int*)  d_in[1];
    const float* emb       = (const float*)d_in[2];
    const float* char_P    = (const float*)d_in[3];
    const float* M1        = (const float*)d_in[4];
    const float* P1        = (const float*)d_in[5];
    const float* g1        = (const float*)d_in[6];
    const float* b1        = (const float*)d_in[7];
    const float* R1        = (const float*)d_in[8];
    const float* M2        = (const float*)d_in[9];
    const float* P2        = (const float*)d_in[10];
    const float* g2        = (const float*)d_in[11];
    const float* b2        = (const float*)d_in[12];
    float* out = (float*)d_out;

    cudaFuncSetAttribute(hier_kernel,
                         cudaFuncAttributeMaxDynamicSharedMemorySize, SMEM_BYTES);

    prep_kernel<<<32, 512>>>(char_P, M1, R1, M2, P1, P2);
    hier_kernel<<<S_LEN, 512, SMEM_BYTES>>>(tokens, positions, emb,
                                            g1, b1, g2, b2, out);
}

// round 7
// speedup vs baseline: 3.2491x; 1.1345x over previous
#include <cuda_runtime.h>
#include <cuda_fp16.h>

#define S_LEN 4096
#define TWO_PI_F 6.28318530717958647692f

typedef unsigned long long u64;

// Transposed weights [j][i] + exact reciprocal-period tables (linear [j][i] order)
__device__ float g_cPt[64 * 64];
__device__ float g_M1t[64 * 128];
__device__ float g_R1t[64 * 128];
__device__ float g_M2t[128 * 128];
__device__ float g_P1t[128 * 128];
__device__ float g_P2t[128 * 128];
__device__ float g_rpDt[128 * 128];  // rpDt[j*128+i] = 1/(i*128+j+2)
__device__ float g_rpVt[64 * 64];    // rpVt[j*64+i]  = 1/(i*64+j+2)

__global__ void prep_kernel(
    const float* __restrict__ cP, const float* __restrict__ M1,
    const float* __restrict__ R1, const float* __restrict__ M2,
    const float* __restrict__ P1, const float* __restrict__ P2)
{
    int t = blockIdx.x * blockDim.x + threadIdx.x;
    if (t < 16384) {
        int i = t >> 7, j = t & 127;
        g_M2t[j * 128 + i] = M2[t];
        g_P1t[j * 128 + i] = P1[t];
        g_P2t[j * 128 + i] = P2[t];
        g_rpDt[t] = 1.0f / (float)((t & 127) * 128 + (t >> 7) + 2);
    }
    if (t < 8192) {
        int i = t >> 6, j = t & 63;
        g_M1t[j * 128 + i] = M1[t];
        g_R1t[j * 128 + i] = R1[t];
    }
    if (t < 4096) {
        int i = t >> 6, j = t & 63;
        g_cPt[j * 64 + i] = cP[t];
        g_rpVt[t] = 1.0f / (float)((t & 63) * 64 + (t >> 6) + 2);
    }
}

__device__ __forceinline__ float pcos(float sf, float rp)
{
    float f = sf * rp;
    float n = rintf(f);
    float r = fmaf(sf, rp, -n);
    return __cosf(TWO_PI_F * r);
}

// ---- packed f32x2 helpers (Blackwell); payload carried in u64 ----
__device__ __forceinline__ u64 fma2(u64 a, u64 b, u64 c)
{ u64 d; asm("fma.rn.f32x2 %0, %1, %2, %3;" : "=l"(d) : "l"(a), "l"(b), "l"(c)); return d; }
__device__ __forceinline__ u64 mul2(u64 a, u64 b)
{ u64 d; asm("mul.rn.f32x2 %0, %1, %2;" : "=l"(d) : "l"(a), "l"(b)); return d; }
__device__ __forceinline__ u64 add2(u64 a, u64 b)
{ u64 d; asm("add.rn.f32x2 %0, %1, %2;" : "=l"(d) : "l"(a), "l"(b)); return d; }
__device__ __forceinline__ u64 bcast2(float x)
{ u64 d; asm("mov.b64 %0, {%1, %1};" : "=l"(d) : "f"(x)); return d; }
__device__ __forceinline__ u64 f2d(float2 v)
{ u64 d; asm("mov.b64 %0, {%1, %2};" : "=l"(d) : "f"(v.x), "f"(v.y)); return d; }
__device__ __forceinline__ float2 d2f(u64 d)
{ float2 v; asm("mov.b64 {%0, %1}, %2;" : "=f"(v.x), "=f"(v.y) : "l"(d)); return v; }

__device__ __forceinline__ float warpsum(float v)
{
#pragma unroll
    for (int o = 16; o > 0; o >>= 1) v += __shfl_xor_sync(0xffffffffu, v, o);
    return v;
}

// smem layout (float index units)
#define OFF_PHI  0          // 16384 halves = 8192 floats
#define OFF_PART 8192       // 4096 u64 = 8192 floats
#define OFF_XST  16384      // 256
#define OFF_HST  16640      // 256
#define OFF_LN1  16896      // 512
#define OFF_H1S  17408      // 512
#define OFF_LN2  17920      // 512
#define OFF_WSM  18432      // 16
#define OFF_WSQ  18448      // 16
#define SM_FLOATS 18464
#define SMEM_BYTES (SM_FLOATS * 4)

// weight-only step: one j, 4 batches x 4 i via 8 f32x2 FMAs
#define WSTEP(W, ACT, J) {                                              \
    float4 w4 = *(const float4*)&W[(J) * 128 + i4];                     \
    ulonglong2 wd = *(ulonglong2*)&w4;                                  \
    float4 a = *(const float4*)&ACT[(J) * 4];                           \
    u64 q0 = bcast2(a.x), q1 = bcast2(a.y);                             \
    u64 q2 = bcast2(a.z), q3 = bcast2(a.w);                             \
    A0h0 = fma2(wd.x, q0, A0h0); A0h1 = fma2(wd.y, q0, A0h1);           \
    A1h0 = fma2(wd.x, q1, A1h0); A1h1 = fma2(wd.y, q1, A1h1);           \
    A2h0 = fma2(wd.x, q2, A2h0); A2h1 = fma2(wd.y, q2, A2h1);           \
    A3h0 = fma2(wd.x, q3, A3h0); A3h1 = fma2(wd.y, q3, A3h1); }

// phase-modulated step: weight * fp16-phi, then 8 f32x2 FMAs
#define PSTEP(W, ACT, J) {                                              \
    float4 w4 = *(const float4*)&W[(J) * 128 + i4];                     \
    ulonglong2 wd = *(ulonglong2*)&w4;                                  \
    uint2 pu = *(const uint2*)&phi16[(J) * 128 + i4];                   \
    float2 p0 = __half22float2(*(__half2*)&pu.x);                       \
    float2 p1 = __half22float2(*(__half2*)&pu.y);                       \
    u64 w0 = mul2(wd.x, f2d(p0));                                       \
    u64 w1 = mul2(wd.y, f2d(p1));                                       \
    float4 a = *(const float4*)&ACT[(J) * 4];                           \
    u64 q0 = bcast2(a.x), q1 = bcast2(a.y);                             \
    u64 q2 = bcast2(a.z), q3 = bcast2(a.w);                             \
    A0h0 = fma2(w0, q0, A0h0); A0h1 = fma2(w1, q0, A0h1);               \
    A1h0 = fma2(w0, q1, A1h0); A1h1 = fma2(w1, q1, A1h1);               \
    A2h0 = fma2(w0, q2, A2h0); A2h1 = fma2(w1, q2, A2h1);               \
    A3h0 = fma2(w0, q3, A3h0); A3h1 = fma2(w1, q3, A3h1); }

#define DECL_ACC u64 A0h0=0, A0h1=0, A1h0=0, A1h1=0,                    \
                     A2h0=0, A2h1=0, A3h0=0, A3h1=0;

#define STOREP() {                                                      \
    ulonglong2 s0; s0.x = A0h0; s0.y = A0h1;                            \
    *(ulonglong2*)&partd[0 * 1024 + js * 64 + (i4 >> 1)] = s0;          \
    ulonglong2 s1; s1.x = A1h0; s1.y = A1h1;                            \
    *(ulonglong2*)&partd[1 * 1024 + js * 64 + (i4 >> 1)] = s1;          \
    ulonglong2 s2; s2.x = A2h0; s2.y = A2h1;                            \
    *(ulonglong2*)&partd[2 * 1024 + js * 64 + (i4 >> 1)] = s2;          \
    ulonglong2 s3; s3.x = A3h0; s3.y = A3h1;                            \
    *(ulonglong2*)&partd[3 * 1024 + js * 64 + (i4 >> 1)] = s3; }

__global__ __launch_bounds__(512, 2)
void hier_kernel(const int*   __restrict__ tokens,
                 const int*   __restrict__ positions,
                 const float* __restrict__ emb,
                 const float* __restrict__ g1, const float* __restrict__ b1,
                 const float* __restrict__ g2, const float* __restrict__ b2,
                 float*       __restrict__ out)
{
    extern __shared__ __align__(16) float sm[];
    __half* phi16 = (__half*)(sm + OFF_PHI);     // [j][i], 128x128
    u64*    partd = (u64*)(sm + OFF_PART);       // [b][slice][i2]
    float*  xsT   = sm + OFF_XST;                // [j][4b]
    float*  hsT   = sm + OFF_HST;                // [j][4b]
    float*  ln1T  = sm + OFF_LN1;                // [j][4b]
    float*  h1sT  = sm + OFF_H1S;                // [j][4b]
    float*  ln2T  = sm + OFF_LN2;                // [j][4b]
    float*  wsm   = sm + OFF_WSM;
    float*  wsq   = sm + OFF_WSQ;

    const int tid = threadIdx.x;
    const int s   = blockIdx.x;
    const float sf = (float)positions[s];

    // ---- build fp16 phiD[j][i] ----
#pragma unroll
    for (int n = 0; n < 8; ++n) {
        int k = n * 2048 + tid * 4;
        float4 rp = *(const float4*)&g_rpDt[k];
        __half2 h0 = __floats2half2_rn(pcos(sf, rp.x), pcos(sf, rp.y));
        __half2 h1 = __floats2half2_rn(pcos(sf, rp.z), pcos(sf, rp.w));
        union { uint2 u; __half2 h[2]; } pk;
        pk.h[0] = h0; pk.h[1] = h1;
        *(uint2*)&phi16[k] = pk.u;
    }

    // ---- gather embeddings: xsT[j][b] ----
    if (tid < 256) {
        int b0 = tid >> 6, j0 = tid & 63;
        int tok = tokens[b0 * S_LEN + s];
        xsT[j0 * 4 + b0] = emb[tok * 64 + j0];
    }
    __syncthreads();

    // =====================================================================
    // Layer 0 (V=64): 64 i x 8 j-slices of 8, f32x2 over batch pairs
    // =====================================================================
    {
        const int i = tid & 63, sl = tid >> 6;
        u64 a01 = 0, a23 = 0;
#pragma unroll
        for (int jj = 0; jj < 8; ++jj) {
            int j = sl * 8 + jj;
            float pw = g_cPt[j * 64 + i] * pcos(sf, g_rpVt[j * 64 + i]);
            u64 p2 = bcast2(pw);
            float4 a = *(const float4*)&xsT[j * 4];
            ulonglong2 ad = *(ulonglong2*)&a;
            a01 = fma2(p2, ad.x, a01);
            a23 = fma2(p2, ad.y, a23);
        }
        ulonglong2 st; st.x = a01; st.y = a23;
        *(ulonglong2*)&partd[sl * 128 + i * 2] = st;
    }
    __syncthreads();
    if (tid < 128) {
        int i = tid >> 1, pp = tid & 1;
        u64 v = 0;
#pragma unroll
        for (int sl = 0; sl < 8; ++sl) v = add2(v, partd[sl * 128 + i * 2 + pp]);
        float2 f = d2f(v);
        hsT[i * 4 + pp * 2 + 0] = f.x;
        hsT[i * 4 + pp * 2 + 1] = f.y;
    }
    __syncthreads();

    // D-stage mapping: warp = j-slice, lanes cover 128 i as float4
    const int js = tid >> 5;          // 0..15
    const int i4 = (tid & 31) * 4;    // float4 i-base
    // reduce mapping (tid < 256): b, i-pair
    const int rb  = tid >> 6;         // 0..3
    const int ri2 = tid & 63;         // i-pair index

    // =====================================================================
    // t1 = M1 @ h : 64 j, slice of 4
    // =====================================================================
    {
        DECL_ACC;
        const int j0 = js * 4;
        WSTEP(g_M1t, hsT, j0 + 0); WSTEP(g_M1t, hsT, j0 + 1);
        WSTEP(g_M1t, hsT, j0 + 2); WSTEP(g_M1t, hsT, j0 + 3);
        STOREP();
    }
    __syncthreads();

    // ---- reduce t1 + LayerNorm 1 ----
    if (tid < 256) {
        u64 v = 0;
#pragma unroll
        for (int sl = 0; sl < 16; ++sl)
            v = add2(v, partd[rb * 1024 + sl * 64 + ri2]);
        float2 f = d2f(v);
        float sm_ = warpsum(f.x + f.y);
        float sq_ = warpsum(fmaf(f.x, f.x, f.y * f.y));
        if ((tid & 31) == 0) { wsm[tid >> 5] = sm_; wsq[tid >> 5] = sq_; }
        partd[rb * 1024 + ri2] = v;   // stash for post-sync LN write
    }
    __syncthreads();
    if (tid < 256) {
        float mean = (wsm[rb * 2] + wsm[rb * 2 + 1]) * 0.0078125f;
        float ex2  = (wsq[rb * 2] + wsq[rb * 2 + 1]) * 0.0078125f;
        float rstd = rsqrtf(fmaf(-mean, mean, ex2) + 1e-5f);
        float2 f = d2f(partd[rb * 1024 + ri2]);
        float2 gg = *(const float2*)&g1[ri2 * 2];
        float2 bb = *(const float2*)&b1[ri2 * 2];
        ln1T[(2 * ri2)     * 4 + rb] = (f.x - mean) * rstd * gg.x + bb.x;
        ln1T[(2 * ri2 + 1) * 4 + rb] = (f.y - mean) * rstd * gg.y + bb.y;
    }
    __syncthreads();

    // =====================================================================
    // h1 = posnk(ln1, P1, phiD) + R1 @ h : 8 j (P) + 4 j (R) per slice
    // =====================================================================
    {
        DECL_ACC;
        const int j0 = js * 8;
        PSTEP(g_P1t, ln1T, j0 + 0); PSTEP(g_P1t, ln1T, j0 + 1);
        PSTEP(g_P1t, ln1T, j0 + 2); PSTEP(g_P1t, ln1T, j0 + 3);
        PSTEP(g_P1t, ln1T, j0 + 4); PSTEP(g_P1t, ln1T, j0 + 5);
        PSTEP(g_P1t, ln1T, j0 + 6); PSTEP(g_P1t, ln1T, j0 + 7);
        const int jr = js * 4;
        WSTEP(g_R1t, hsT, jr + 0); WSTEP(g_R1t, hsT, jr + 1);
        WSTEP(g_R1t, hsT, jr + 2); WSTEP(g_R1t, hsT, jr + 3);
        STOREP();
    }
    __syncthreads();
    if (tid < 256) {
        u64 v = 0;
#pragma unroll
        for (int sl = 0; sl < 16; ++sl)
            v = add2(v, partd[rb * 1024 + sl * 64 + ri2]);
        float2 f = d2f(v);
        h1sT[(2 * ri2)     * 4 + rb] = f.x;
        h1sT[(2 * ri2 + 1) * 4 + rb] = f.y;
    }
    __syncthreads();

    // =====================================================================
    // t2 = M2 @ h1 : 8 j per slice
    // =====================================================================
    {
        DECL_ACC;
        const int j0 = js * 8;
        WSTEP(g_M2t, h1sT, j0 + 0); WSTEP(g_M2t, h1sT, j0 + 1);
        WSTEP(g_M2t, h1sT, j0 + 2); WSTEP(g_M2t, h1sT, j0 + 3);
        WSTEP(g_M2t, h1sT, j0 + 4); WSTEP(g_M2t, h1sT, j0 + 5);
        WSTEP(g_M2t, h1sT, j0 + 6); WSTEP(g_M2t, h1sT, j0 + 7);
        STOREP();
    }
    __syncthreads();

    // ---- reduce t2 + LayerNorm 2 (t2 pair kept in register for residual) ----
    u64 t2d = 0;
    if (tid < 256) {
#pragma unroll
        for (int sl = 0; sl < 16; ++sl)
            t2d = add2(t2d, partd[rb * 1024 + sl * 64 + ri2]);
        float2 f = d2f(t2d);
        float sm_ = warpsum(f.x + f.y);
        float sq_ = warpsum(fmaf(f.x, f.x, f.y * f.y));
        if ((tid & 31) == 0) { wsm[tid >> 5] = sm_; wsq[tid >> 5] = sq_; }
    }
    __syncthreads();
    if (tid < 256) {
        float mean = (wsm[rb * 2] + wsm[rb * 2 + 1]) * 0.0078125f;
        float ex2  = (wsq[rb * 2] + wsq[rb * 2 + 1]) * 0.0078125f;
        float rstd = rsqrtf(fmaf(-mean, mean, ex2) + 1e-5f);
        float2 f = d2f(t2d);
        float2 gg = *(const float2*)&g2[ri2 * 2];
        float2 bb = *(const float2*)&b2[ri2 * 2];
        ln2T[(2 * ri2)     * 4 + rb] = (f.x - mean) * rstd * gg.x + bb.x;
        ln2T[(2 * ri2 + 1) * 4 + rb] = (f.y - mean) * rstd * gg.y + bb.y;
    }
    __syncthreads();

    // =====================================================================
    // out = posnk(ln2, P2, phiD) + t2
    // =====================================================================
    {
        DECL_ACC;
        const int j0 = js * 8;
        PSTEP(g_P2t, ln2T, j0 + 0); PSTEP(g_P2t, ln2T, j0 + 1);
        PSTEP(g_P2t, ln2T, j0 + 2); PSTEP(g_P2t, ln2T, j0 + 3);
        PSTEP(g_P2t, ln2T, j0 + 4); PSTEP(g_P2t, ln2T, j0 + 5);
        PSTEP(g_P2t, ln2T, j0 + 6); PSTEP(g_P2t, ln2T, j0 + 7);
        STOREP();
    }
    __syncthreads();
    if (tid < 256) {
        u64 v = t2d;
#pragma unroll
        for (int sl = 0; sl < 16; ++sl)
            v = add2(v, partd[rb * 1024 + sl * 64 + ri2]);
        float2 f = d2f(v);
        *(float2*)&out[((size_t)rb * S_LEN + s) * 128 + 2 * ri2] = f;
    }
}

extern "C" void kernel_launch(void* const* d_in, const int* in_sizes, int n_in,
                              void* d_out, int out_size)
{
    const int*   tokens    = (const int*)  d_in[0];
    const int*   positions = (const int*)  d_in[1];
    const float* emb       = (const float*)d_in[2];
    const float* char_P    = (const float*)d_in[3];
    const float* M1        = (const float*)d_in[4];
    const float* P1        = (const float*)d_in[5];
    const float* g1        = (const float*)d_in[6];
    const float* b1        = (const float*)d_in[7];
    const float* R1        = (const float*)d_in[8];
    const float* M2        = (const float*)d_in[9];
    const float* P2        = (const float*)d_in[10];
    const float* g2        = (const float*)d_in[11];
    const float* b2        = (const float*)d_in[12];
    float* out = (float*)d_out;

    cudaFuncSetAttribute(hier_kernel,
                         cudaFuncAttributeMaxDynamicSharedMemorySize, SMEM_BYTES);

    prep_kernel<<<32, 512>>>(char_P, M1, R1, M2, P1, P2);
    hier_kernel<<<S_LEN, 512, SMEM_BYTES>>>(tokens, positions, emb,
                                            g1, b1, g2, b2, out);
}

// round 10
// speedup vs baseline: 3.4959x; 1.0760x over previous
#include <cuda_runtime.h>
#include <cuda_fp16.h>

#define S_LEN 4096
#define TWO_PI_F 6.28318530717958647692f

typedef unsigned long long u64;

// fp16 transposed weights [j][i]; fp32 cP + reciprocal-period tables
__device__ float  g_cPt[64 * 64];      // fp32 [j][i]
__device__ __half g_M1h[64 * 128];
__device__ __half g_R1h[64 * 128];
__device__ __half g_M2h[128 * 128];
__device__ __half g_P1h[128 * 128];
__device__ __half g_P2h[128 * 128];
__device__ float  g_rpDt[128 * 128];   // [j][i] = 1/(i*128+j+2)
__device__ float  g_rpVt[64 * 64];     // [j][i] = 1/(i*64+j+2)

__global__ void prep_kernel(
    const float* __restrict__ cP, const float* __restrict__ M1,
    const float* __restrict__ R1, const float* __restrict__ M2,
    const float* __restrict__ P1, const float* __restrict__ P2)
{
    int t = blockIdx.x * blockDim.x + threadIdx.x;
    if (t < 16384) {
        int i = t >> 7, j = t & 127;
        g_M2h[j * 128 + i] = __float2half_rn(M2[t]);
        g_P1h[j * 128 + i] = __float2half_rn(P1[t]);
        g_P2h[j * 128 + i] = __float2half_rn(P2[t]);
        g_rpDt[t] = 1.0f / (float)((t & 127) * 128 + (t >> 7) + 2);
    }
    if (t < 8192) {
        int i = t >> 6, j = t & 63;
        g_M1h[j * 128 + i] = __float2half_rn(M1[t]);
        g_R1h[j * 128 + i] = __float2half_rn(R1[t]);
    }
    if (t < 4096) {
        int i = t >> 6, j = t & 63;
        g_cPt[j * 64 + i] = cP[t];
        g_rpVt[t] = 1.0f / (float)((t & 63) * 64 + (t >> 6) + 2);
    }
}

__device__ __forceinline__ float pcos(float sf, float rp)
{
    float f = sf * rp;
    float n = rintf(f);
    float r = fmaf(sf, rp, -n);
    return __cosf(TWO_PI_F * r);
}

// ---- packed f32x2 helpers; payload in u64 ----
__device__ __forceinline__ u64 fma2(u64 a, u64 b, u64 c)
{ u64 d; asm("fma.rn.f32x2 %0, %1, %2, %3;" : "=l"(d) : "l"(a), "l"(b), "l"(c)); return d; }
__device__ __forceinline__ u64 mul2(u64 a, u64 b)
{ u64 d; asm("mul.rn.f32x2 %0, %1, %2;" : "=l"(d) : "l"(a), "l"(b)); return d; }
__device__ __forceinline__ u64 add2(u64 a, u64 b)
{ u64 d; asm("add.rn.f32x2 %0, %1, %2;" : "=l"(d) : "l"(a), "l"(b)); return d; }
__device__ __forceinline__ u64 bcast2(float x)
{ u64 d; asm("mov.b64 %0, {%1, %1};" : "=l"(d) : "f"(x)); return d; }
__device__ __forceinline__ u64 f2d(float2 v)
{ u64 d; asm("mov.b64 %0, {%1, %2};" : "=l"(d) : "f"(v.x), "f"(v.y)); return d; }
__device__ __forceinline__ float2 d2f(u64 d)
{ float2 v; asm("mov.b64 {%0, %1}, %2;" : "=f"(v.x), "=f"(v.y) : "l"(d)); return v; }

__device__ __forceinline__ float warpsum(float v)
{
#pragma unroll
    for (int o = 16; o > 0; o >>= 1) v += __shfl_xor_sync(0xffffffffu, v, o);
    return v;
}

// smem layout (float index units)
#define OFF_PHI  0          // 16384 halves = 8192 floats
#define OFF_PART 8192       // 2048 u64 = 4096 floats
#define OFF_XST  12288      // 256
#define OFF_HST  12544      // 256
#define OFF_LN1  12800      // 512
#define OFF_H1S  13312      // 512
#define OFF_LN2  13824      // 512
#define OFF_WSM  14336      // 16
#define OFF_WSQ  14352      // 16
#define SM_FLOATS 14368
#define SMEM_BYTES (SM_FLOATS * 4)

// fp16-weight step: one j, 4 batches x 2 i (i-pair) via 4 f32x2 FMAs
#define WSTEP8(W, ACT, J) {                                             \
    unsigned wu = *(const unsigned*)&W[(J) * 128 + 2 * i2];             \
    u64 wd = f2d(__half22float2(*(__half2*)&wu));                       \
    float4 a = *(const float4*)&ACT[(J) * 4];                           \
    A0 = fma2(wd, bcast2(a.x), A0);                                     \
    A1 = fma2(wd, bcast2(a.y), A1);                                     \
    A2 = fma2(wd, bcast2(a.z), A2);                                     \
    A3 = fma2(wd, bcast2(a.w), A3); }

// phase-modulated fp16-weight step
#define PSTEP8(W, ACT, J) {                                             \
    unsigned wu = *(const unsigned*)&W[(J) * 128 + 2 * i2];             \
    unsigned pu = *(const unsigned*)&phi16[(J) * 128 + 2 * i2];         \
    u64 wd = mul2(f2d(__half22float2(*(__half2*)&wu)),                  \
                  f2d(__half22float2(*(__half2*)&pu)));                 \
    float4 a = *(const float4*)&ACT[(J) * 4];                           \
    A0 = fma2(wd, bcast2(a.x), A0);                                     \
    A1 = fma2(wd, bcast2(a.y), A1);                                     \
    A2 = fma2(wd, bcast2(a.z), A2);                                     \
    A3 = fma2(wd, bcast2(a.w), A3); }

#define DECL_ACC u64 A0 = 0, A1 = 0, A2 = 0, A3 = 0;

// partials layout: [js][b][i2] u64, js<8, b<4, i2<64
#define STOREP8() {                                                     \
    partd[js8 * 256 + 0 * 64 + i2] = A0;                                \
    partd[js8 * 256 + 1 * 64 + i2] = A1;                                \
    partd[js8 * 256 + 2 * 64 + i2] = A2;                                \
    partd[js8 * 256 + 3 * 64 + i2] = A3; }

__global__ __launch_bounds__(512, 2)
void hier_kernel(const int*   __restrict__ tokens,
                 const int*   __restrict__ positions,
                 const float* __restrict__ emb,
                 const float* __restrict__ g1, const float* __restrict__ b1,
                 const float* __restrict__ g2, const float* __restrict__ b2,
                 float*       __restrict__ out)
{
    extern __shared__ __align__(16) float sm[];
    __half* phi16 = (__half*)(sm + OFF_PHI);     // [j][i] 128x128
    u64*    partd = (u64*)(sm + OFF_PART);       // [js][b][i2]
    float*  xsT   = sm + OFF_XST;                // [j][4b]
    float*  hsT   = sm + OFF_HST;                // [j][4b]
    float*  ln1T  = sm + OFF_LN1;                // [j][4b]
    float*  h1sT  = sm + OFF_H1S;                // [j][4b]
    float*  ln2T  = sm + OFF_LN2;                // [j][4b]
    float*  wsm   = sm + OFF_WSM;
    float*  wsq   = sm + OFF_WSQ;

    const int tid = threadIdx.x;
    const int s   = blockIdx.x;
    const float sf = (float)positions[s];

    // ---- build fp16 phiD[j][i] ----
#pragma unroll
    for (int n = 0; n < 8; ++n) {
        int k = n * 2048 + tid * 4;
        float4 rp = *(const float4*)&g_rpDt[k];
        __half2 h0 = __floats2half2_rn(pcos(sf, rp.x), pcos(sf, rp.y));
        __half2 h1 = __floats2half2_rn(pcos(sf, rp.z), pcos(sf, rp.w));
        union { uint2 u; __half2 h[2]; } pk;
        pk.h[0] = h0; pk.h[1] = h1;
        *(uint2*)&phi16[k] = pk.u;
    }

    // ---- gather embeddings: xsT[j][b] ----
    if (tid < 256) {
        int b0 = tid >> 6, j0 = tid & 63;
        int tok = tokens[b0 * S_LEN + s];
        xsT[j0 * 4 + b0] = emb[tok * 64 + j0];
    }
    __syncthreads();

    // =====================================================================
    // Layer 0 (V=64): 64 i x 8 j-slices of 8, f32x2 over batch pairs
    // =====================================================================
    {
        const int i = tid & 63, sl = tid >> 6;
        u64 a01 = 0, a23 = 0;
#pragma unroll
        for (int jj = 0; jj < 8; ++jj) {
            int j = sl * 8 + jj;
            float pw = g_cPt[j * 64 + i] * pcos(sf, g_rpVt[j * 64 + i]);
            u64 p2 = bcast2(pw);
            float4 a = *(const float4*)&xsT[j * 4];
            ulonglong2 ad = *(ulonglong2*)&a;
            a01 = fma2(p2, ad.x, a01);
            a23 = fma2(p2, ad.y, a23);
        }
        ulonglong2 st; st.x = a01; st.y = a23;
        *(ulonglong2*)&partd[sl * 128 + i * 2] = st;
    }
    __syncthreads();
    if (tid < 128) {
        int i = tid >> 1, pp = tid & 1;
        u64 v = 0;
#pragma unroll
        for (int sl = 0; sl < 8; ++sl) v = add2(v, partd[sl * 128 + i * 2 + pp]);
        float2 f = d2f(v);
        hsT[i * 4 + pp * 2 + 0] = f.x;
        hsT[i * 4 + pp * 2 + 1] = f.y;
    }
    __syncthreads();

    // D-stage mapping: warp = (i-half, j-slice); lane carries i-pair
    const int w    = tid >> 5;
    const int ih   = w & 1;
    const int js8  = w >> 1;                 // 0..7
    const int i2   = ih * 32 + (tid & 31);   // i-pair 0..63
    // reduce mapping (tid < 256): b, i-pair
    const int rb   = tid >> 6;               // 0..3
    const int ri2  = tid & 63;

    // =====================================================================
    // t1 = M1 @ h : 64 j, slice of 8
    // =====================================================================
    {
        DECL_ACC;
        const int j0 = js8 * 8;
#pragma unroll
        for (int k = 0; k < 8; ++k) WSTEP8(g_M1h, hsT, j0 + k);
        STOREP8();
    }
    __syncthreads();

    // ---- reduce t1 + LayerNorm 1 ----
    if (tid < 256) {
        u64 v = 0;
#pragma unroll
        for (int sl = 0; sl < 8; ++sl)
            v = add2(v, partd[sl * 256 + rb * 64 + ri2]);
        float2 f = d2f(v);
        float sm_ = warpsum(f.x + f.y);
        float sq_ = warpsum(fmaf(f.x, f.x, f.y * f.y));
        if ((tid & 31) == 0) { wsm[tid >> 5] = sm_; wsq[tid >> 5] = sq_; }
        partd[1792 + rb * 64 + ri2] = v;   // stash (slice-7 slot unused after read)
    }
    __syncthreads();
    if (tid < 256) {
        float mean = (wsm[rb * 2] + wsm[rb * 2 + 1]) * 0.0078125f;
        float ex2  = (wsq[rb * 2] + wsq[rb * 2 + 1]) * 0.0078125f;
        float rstd = rsqrtf(fmaf(-mean, mean, ex2) + 1e-5f);
        float2 f = d2f(partd[1792 + rb * 64 + ri2]);
        float2 gg = *(const float2*)&g1[ri2 * 2];
        float2 bb = *(const float2*)&b1[ri2 * 2];
        ln1T[(2 * ri2)     * 4 + rb] = (f.x - mean) * rstd * gg.x + bb.x;
        ln1T[(2 * ri2 + 1) * 4 + rb] = (f.y - mean) * rstd * gg.y + bb.y;
    }
    __syncthreads();

    // =====================================================================
    // h1 = posnk(ln1, P1, phiD) + R1 @ h : 16 j (P) + 8 j (R) per slice
    // =====================================================================
    {
        DECL_ACC;
        const int j0 = js8 * 16;
#pragma unroll
        for (int k = 0; k < 16; ++k) PSTEP8(g_P1h, ln1T, j0 + k);
        const int jr = js8 * 8;
#pragma unroll
        for (int k = 0; k < 8; ++k) WSTEP8(g_R1h, hsT, jr + k);
        STOREP8();
    }
    __syncthreads();
    if (tid < 256) {
        u64 v = 0;
#pragma unroll
        for (int sl = 0; sl < 8; ++sl)
            v = add2(v, partd[sl * 256 + rb * 64 + ri2]);
        float2 f = d2f(v);
        h1sT[(2 * ri2)     * 4 + rb] = f.x;
        h1sT[(2 * ri2 + 1) * 4 + rb] = f.y;
    }
    __syncthreads();

    // =====================================================================
    // t2 = M2 @ h1 : 16 j per slice
    // =====================================================================
    {
        DECL_ACC;
        const int j0 = js8 * 16;
#pragma unroll
        for (int k = 0; k < 16; ++k) WSTEP8(g_M2h, h1sT, j0 + k);
        STOREP8();
    }
    __syncthreads();

    // ---- reduce t2 + LayerNorm 2 (t2 pair kept in register for residual) ----
    u64 t2d = 0;
    if (tid < 256) {
#pragma unroll
        for (int sl = 0; sl < 8; ++sl)
            t2d = add2(t2d, partd[sl * 256 + rb * 64 + ri2]);
        float2 f = d2f(t2d);
        float sm_ = warpsum(f.x + f.y);
        float sq_ = warpsum(fmaf(f.x, f.x, f.y * f.y));
        if ((tid & 31) == 0) { wsm[tid >> 5] = sm_; wsq[tid >> 5] = sq_; }
    }
    __syncthreads();
    if (tid < 256) {
        float mean = (wsm[rb * 2] + wsm[rb * 2 + 1]) * 0.0078125f;
        float ex2  = (wsq[rb * 2] + wsq[rb * 2 + 1]) * 0.0078125f;
        float rstd = rsqrtf(fmaf(-mean, mean, ex2) + 1e-5f);
        float2 f = d2f(t2d);
        float2 gg = *(const float2*)&g2[ri2 * 2];
        float2 bb = *(const float2*)&b2[ri2 * 2];
        ln2T[(2 * ri2)     * 4 + rb] = (f.x - mean) * rstd * gg.x + bb.x;
        ln2T[(2 * ri2 + 1) * 4 + rb] = (f.y - mean) * rstd * gg.y + bb.y;
    }
    __syncthreads();

    // =====================================================================
    // out = posnk(ln2, P2, phiD) + t2
    // =====================================================================
    {
        DECL_ACC;
        const int j0 = js8 * 16;
#pragma unroll
        for (int k = 0; k < 16; ++k) PSTEP8(g_P2h, ln2T, j0 + k);
        STOREP8();
    }
    __syncthreads();
    if (tid < 256) {
        u64 v = t2d;
#pragma unroll
        for (int sl = 0; sl < 8; ++sl)
            v = add2(v, partd[sl * 256 + rb * 64 + ri2]);
        float2 f = d2f(v);
        *(float2*)&out[((size_t)rb * S_LEN + s) * 128 + 2 * ri2] = f;
    }
}

extern "C" void kernel_launch(void* const* d_in, const int* in_sizes, int n_in,
                              void* d_out, int out_size)
{
    const int*   tokens    = (const int*)  d_in[0];
    const int*   positions = (const int*)  d_in[1];
    const float* emb       = (const float*)d_in[2];
    const float* char_P    = (const float*)d_in[3];
    const float* M1        = (const float*)d_in[4];
    const float* P1        = (const float*)d_in[5];
    const float* g1        = (const float*)d_in[6];
    const float* b1        = (const float*)d_in[7];
    const float* R1        = (const float*)d_in[8];
    const float* M2        = (const float*)d_in[9];
    const float* P2        = (const float*)d_in[10];
    const float* g2        = (const float*)d_in[11];
    const float* b2        = (const float*)d_in[12];
    float* out = (float*)d_out;

    cudaFuncSetAttribute(hier_kernel,
                         cudaFuncAttributeMaxDynamicSharedMemorySize, SMEM_BYTES);

    prep_kernel<<<32, 512>>>(char_P, M1, R1, M2, P1, P2);
    hier_kernel<<<S_LEN, 512, SMEM_BYTES>>>(tokens, positions, emb,
                                            g1, b1, g2, b2, out);
}